// round 2
// baseline (speedup 1.0000x reference)
#include <cuda_runtime.h>
#include <math.h>

#define HEADS 8
#define DIMH  64
#define SEQ   16
#define CH    512
#define BATCH 2048              // b*h*w = 2*32*32
#define MROWS (BATCH*SEQ)       // 32768
#define QKVN  1536
#define MEM   4
#define KVLEN (MEM+SEQ)         // 20

#define MP_INV 1.3130643286f    // 1/sqrt(0.58)

// ------------------------- scratch (device globals) -------------------------
__device__ float g_Y   [(size_t)MROWS*CH];
__device__ float g_RES [(size_t)MROWS*CH];
__device__ float g_ATT [(size_t)MROWS*CH];
__device__ float g_QKV [(size_t)MROWS*QKVN];
__device__ float g_Wqkv[2*QKVN*CH];
__device__ float g_Wout[2*CH*CH];
__device__ float g_Wprj[CH*CH];

// ------------------------- transpose in: x[b,c,t,h,w] -> Y[(b,h,w),t,c] -----
__global__ void transpose_in(const float* __restrict__ x,
                             float* __restrict__ Y, float* __restrict__ RES) {
    __shared__ float tile[32][33];
    const int b  = blockIdx.z;
    const int t  = blockIdx.y >> 5;
    const int i  = blockIdx.y & 31;
    const int c0 = blockIdx.x << 5;
    const int tx = threadIdx.x, ty = threadIdx.y;   // (32,8)

    const float* xp = x + (((size_t)(b*CH + c0)*SEQ + t)*32 + i)*32;
#pragma unroll
    for (int r = 0; r < 4; r++) {
        int cl = ty + r*8;
        tile[cl][tx] = xp[(size_t)cl*SEQ*32*32 + tx];
    }
    __syncthreads();
#pragma unroll
    for (int r = 0; r < 4; r++) {
        int j = ty + r*8;
        size_t off = ((size_t)(b*1024 + i*32 + j)*SEQ + t)*CH + c0 + tx;
        float v = tile[tx][j];
        Y[off] = v; RES[off] = v;
    }
}

// ------------------ transpose out + final mp_add: -> out[b,c,t,h,w] ---------
__global__ void transpose_out(const float* __restrict__ P,
                              const float* __restrict__ RES,
                              float* __restrict__ out) {
    __shared__ float tile[32][33];
    const int b  = blockIdx.z;
    const int t  = blockIdx.y >> 5;
    const int i  = blockIdx.y & 31;
    const int c0 = blockIdx.x << 5;
    const int tx = threadIdx.x, ty = threadIdx.y;

#pragma unroll
    for (int r = 0; r < 4; r++) {
        int j = ty + r*8;
        size_t off = ((size_t)(b*1024 + i*32 + j)*SEQ + t)*CH + c0 + tx;
        tile[tx][j] = (P[off]*0.7f + RES[off]*0.3f) * MP_INV;
    }
    __syncthreads();
    float* op = out + (((size_t)(b*CH + c0)*SEQ + t)*32 + i)*32;
#pragma unroll
    for (int r = 0; r < 4; r++) {
        int cl = ty + r*8;
        op[(size_t)cl*SEQ*32*32 + tx] = tile[cl][tx];
    }
}

// ----------------- weight row l2norm: dst = row/max(||row||,eps)/sqrt(K) ----
__global__ void rownorm(const float* __restrict__ src, float* __restrict__ dst,
                        const float* __restrict__ gain) {
    const int row = blockIdx.x;
    const int t   = threadIdx.x;            // 128 threads, K=512
    const float4 v = ((const float4*)(src + (size_t)row*CH))[t];
    float ss = v.x*v.x + v.y*v.y + v.z*v.z + v.w*v.w;
#pragma unroll
    for (int o = 16; o; o >>= 1) ss += __shfl_xor_sync(0xffffffffu, ss, o);
    __shared__ float red[4];
    __shared__ float sscale;
    if ((t & 31) == 0) red[t >> 5] = ss;
    __syncthreads();
    if (t == 0) {
        float tot = red[0] + red[1] + red[2] + red[3];
        float sc = 1.f / (fmaxf(sqrtf(tot), 1e-4f) * 22.627416998f); // sqrt(512)
        if (gain) sc *= gain[0];
        sscale = sc;
    }
    __syncthreads();
    const float sc = sscale;
    ((float4*)(dst + (size_t)row*CH))[t] =
        make_float4(v.x*sc, v.y*sc, v.z*sc, v.w*sc);
}

// ------------------------- tiled fp32 NT-SGEMM -------------------------------
// C[M,N] = A[M,K] @ B[N,K]^T.  MODE 0: store.  MODE 1: C = (acc*0.7+C*0.3)*MP_INV
template<int MODE>
__global__ void __launch_bounds__(256, 2)
gemm_nt(const float* __restrict__ A, const float* __restrict__ B,
        float* __restrict__ Cm, int N, int K) {
    __shared__ float As[16][128];
    __shared__ float Bs[16][128];
    const int tid = threadIdx.x;
    const int m0  = blockIdx.y << 7;
    const int n0  = blockIdx.x << 7;
    const int lr  = tid >> 2;
    const int lc  = (tid & 3) << 2;
    const float* Ag = A + (size_t)(m0 + lr)*K + lc;
    const float* Bg = B + (size_t)(n0 + lr)*K + lc;
    const int tx = tid & 15;
    const int ty = tid >> 4;

    float acc[8][8];
#pragma unroll
    for (int i = 0; i < 8; i++)
#pragma unroll
        for (int j = 0; j < 8; j++) acc[i][j] = 0.f;

    for (int k0 = 0; k0 < K; k0 += 16) {
        float4 a0 = *(const float4*)(Ag + k0);
        float4 a1 = *(const float4*)(Ag + k0 + (size_t)64*K);
        float4 b0 = *(const float4*)(Bg + k0);
        float4 b1 = *(const float4*)(Bg + k0 + (size_t)64*K);
        As[lc+0][lr]    = a0.x; As[lc+1][lr]    = a0.y; As[lc+2][lr]    = a0.z; As[lc+3][lr]    = a0.w;
        As[lc+0][lr+64] = a1.x; As[lc+1][lr+64] = a1.y; As[lc+2][lr+64] = a1.z; As[lc+3][lr+64] = a1.w;
        Bs[lc+0][lr]    = b0.x; Bs[lc+1][lr]    = b0.y; Bs[lc+2][lr]    = b0.z; Bs[lc+3][lr]    = b0.w;
        Bs[lc+0][lr+64] = b1.x; Bs[lc+1][lr+64] = b1.y; Bs[lc+2][lr+64] = b1.z; Bs[lc+3][lr+64] = b1.w;
        __syncthreads();
#pragma unroll
        for (int kk = 0; kk < 16; kk++) {
            const float4 av0 = *(const float4*)&As[kk][ty*8];
            const float4 av1 = *(const float4*)&As[kk][ty*8 + 4];
            const float4 bv0 = *(const float4*)&Bs[kk][tx*8];
            const float4 bv1 = *(const float4*)&Bs[kk][tx*8 + 4];
            float a[8] = {av0.x,av0.y,av0.z,av0.w,av1.x,av1.y,av1.z,av1.w};
            float b[8] = {bv0.x,bv0.y,bv0.z,bv0.w,bv1.x,bv1.y,bv1.z,bv1.w};
#pragma unroll
            for (int i = 0; i < 8; i++)
#pragma unroll
                for (int j = 0; j < 8; j++) acc[i][j] += a[i]*b[j];
        }
        __syncthreads();
    }

#pragma unroll
    for (int i = 0; i < 8; i++) {
        float* Cr = Cm + (size_t)(m0 + ty*8 + i)*N + n0 + tx*8;
        if (MODE == 0) {
            *(float4*)(Cr)     = make_float4(acc[i][0], acc[i][1], acc[i][2], acc[i][3]);
            *(float4*)(Cr + 4) = make_float4(acc[i][4], acc[i][5], acc[i][6], acc[i][7]);
        } else {
            float4 r0 = *(const float4*)(Cr);
            float4 r1 = *(const float4*)(Cr + 4);
            *(float4*)(Cr) = make_float4(
                (acc[i][0]*0.7f + r0.x*0.3f)*MP_INV, (acc[i][1]*0.7f + r0.y*0.3f)*MP_INV,
                (acc[i][2]*0.7f + r0.z*0.3f)*MP_INV, (acc[i][3]*0.7f + r0.w*0.3f)*MP_INV);
            *(float4*)(Cr + 4) = make_float4(
                (acc[i][4]*0.7f + r1.x*0.3f)*MP_INV, (acc[i][5]*0.7f + r1.y*0.3f)*MP_INV,
                (acc[i][6]*0.7f + r1.z*0.3f)*MP_INV, (acc[i][7]*0.7f + r1.w*0.3f)*MP_INV);
        }
    }
}

// ------------------------- fused attention ----------------------------------
// 1 warp per (seq, head). kn/vn pixel-normed in smem; q l2-normed in regs
// (pixel_norm(q)*sqrt(D) cancels with D^-1/2 scale -> plain l2norm).
__global__ void attention(const float* __restrict__ QKV,
                          const float* __restrict__ memkv,  // [2][8][4][64] for this layer
                          float* __restrict__ ATT) {
    __shared__ float kn[KVLEN][DIMH];
    __shared__ float vn[KVLEN][DIMH];
    const int head = blockIdx.x;
    const int seq  = blockIdx.y;
    const int lane = threadIdx.x;
    const float* memk = memkv;
    const float* memv = memkv + HEADS*MEM*DIMH;

#pragma unroll
    for (int r = 0; r < KVLEN; r++) {
        const float* ks = (r < MEM)
            ? memk + ((size_t)head*MEM + r)*DIMH
            : QKV + ((size_t)seq*SEQ + (r-MEM))*QKVN + CH + head*DIMH;
        float x0 = ks[lane], x1 = ks[lane+32];
        float ss = x0*x0 + x1*x1;
#pragma unroll
        for (int o = 16; o; o >>= 1) ss += __shfl_xor_sync(0xffffffffu, ss, o);
        float s = 8.f / fmaxf(sqrtf(ss), 1e-4f);   // pixel_norm scale
        kn[r][lane] = x0*s; kn[r][lane+32] = x1*s;

        const float* vs = (r < MEM)
            ? memv + ((size_t)head*MEM + r)*DIMH
            : QKV + ((size_t)seq*SEQ + (r-MEM))*QKVN + 2*CH + head*DIMH;
        x0 = vs[lane]; x1 = vs[lane+32];
        ss = x0*x0 + x1*x1;
#pragma unroll
        for (int o = 16; o; o >>= 1) ss += __shfl_xor_sync(0xffffffffu, ss, o);
        s = 8.f / fmaxf(sqrtf(ss), 1e-4f);
        vn[r][lane] = x0*s; vn[r][lane+32] = x1*s;
    }
    __syncwarp();

    if (lane < SEQ) {
        const float4* qp = (const float4*)(QKV + ((size_t)seq*SEQ + lane)*QKVN + head*DIMH);
        float q[DIMH];
        float ss = 0.f;
#pragma unroll
        for (int d4 = 0; d4 < DIMH/4; d4++) {
            float4 v = qp[d4];
            q[4*d4+0]=v.x; q[4*d4+1]=v.y; q[4*d4+2]=v.z; q[4*d4+3]=v.w;
            ss += v.x*v.x + v.y*v.y + v.z*v.z + v.w*v.w;
        }
        const float qs = 1.f / fmaxf(sqrtf(ss), 1e-4f);

        float sc[KVLEN];
        float mx = -1e30f;
#pragma unroll
        for (int j = 0; j < KVLEN; j++) {
            float dot = 0.f;
#pragma unroll
            for (int d = 0; d < DIMH; d++) dot += q[d]*kn[j][d];
            dot *= qs;
            sc[j] = dot;
            mx = fmaxf(mx, dot);
        }
        float sum = 0.f;
#pragma unroll
        for (int j = 0; j < KVLEN; j++) { sc[j] = expf(sc[j] - mx); sum += sc[j]; }
        const float inv = 1.f / sum;

        float o[DIMH];
#pragma unroll
        for (int d = 0; d < DIMH; d++) o[d] = 0.f;
#pragma unroll
        for (int j = 0; j < KVLEN; j++) {
            float p = sc[j];
#pragma unroll
            for (int d = 0; d < DIMH; d++) o[d] += p * vn[j][d];
        }
        float4* op = (float4*)(ATT + ((size_t)seq*SEQ + lane)*CH + head*DIMH);
#pragma unroll
        for (int d4 = 0; d4 < DIMH/4; d4++)
            op[d4] = make_float4(o[4*d4]*inv, o[4*d4+1]*inv, o[4*d4+2]*inv, o[4*d4+3]*inv);
    }
}

// ------------------------------- launcher ------------------------------------
extern "C" void kernel_launch(void* const* d_in, const int* in_sizes, int n_in,
                              void* d_out, int out_size) {
    const float* x      = (const float*)d_in[0];
    const float* w_qkv  = (const float*)d_in[1];
    const float* w_out  = (const float*)d_in[2];
    const float* mem_kv = (const float*)d_in[3];
    const float* w_proj = (const float*)d_in[4];
    const float* gain   = (const float*)d_in[5];
    float* out = (float*)d_out;

    float *Y, *RES, *ATT, *QKV, *Wq, *Wo, *Wp;
    cudaGetSymbolAddress((void**)&Y,   g_Y);
    cudaGetSymbolAddress((void**)&RES, g_RES);
    cudaGetSymbolAddress((void**)&ATT, g_ATT);
    cudaGetSymbolAddress((void**)&QKV, g_QKV);
    cudaGetSymbolAddress((void**)&Wq,  g_Wqkv);
    cudaGetSymbolAddress((void**)&Wo,  g_Wout);
    cudaGetSymbolAddress((void**)&Wp,  g_Wprj);

    const dim3 tb(32, 8);
    const dim3 tg(16, 512, 2);        // (c-tiles, t*h, b)

    transpose_in<<<tg, tb>>>(x, Y, RES);

    rownorm<<<2*QKVN, 128>>>(w_qkv,  Wq, nullptr);
    rownorm<<<2*CH,   128>>>(w_out,  Wo, nullptr);
    rownorm<<<CH,     128>>>(w_proj, Wp, gain);

    for (int l = 0; l < 2; l++) {
        gemm_nt<0><<<dim3(QKVN/128, MROWS/128), 256>>>(
            Y, Wq + (size_t)l*QKVN*CH, QKV, QKVN, CH);
        attention<<<dim3(HEADS, BATCH), 32>>>(
            QKV, mem_kv + (size_t)l*2*HEADS*MEM*DIMH, ATT);
        gemm_nt<1><<<dim3(CH/128, MROWS/128), 256>>>(
            ATT, Wo + (size_t)l*CH*CH, Y, CH, CH);
    }

    gemm_nt<0><<<dim3(CH/128, MROWS/128), 256>>>(Y, Wp, QKV, CH, CH);
    transpose_out<<<tg, tb>>>(QKV, RES, out);
}

// round 6
// speedup vs baseline: 2.1668x; 2.1668x over previous
#include <cuda_runtime.h>
#include <cuda_bf16.h>
#include <math.h>
#include <stdint.h>

#define HEADS 8
#define DIMH  64
#define SEQ   16
#define CH    512
#define BATCH 2048              // b*h*w
#define MROWS (BATCH*SEQ)       // 32768
#define QKVN  1536
#define MEM   4
#define KVLEN 20
#define MP_INV 1.3130643286f    // 1/sqrt(0.58)

typedef __nv_bfloat16 bf16;

// ------------------------- scratch (device globals) -------------------------
__device__ float g_Y   [(size_t)MROWS*CH];
__device__ float g_RES [(size_t)MROWS*CH];
__device__ float g_QKV [(size_t)MROWS*QKVN];
__device__ bf16  g_Yh  [(size_t)MROWS*CH];
__device__ bf16  g_Yl  [(size_t)MROWS*CH];
__device__ bf16  g_ATh [(size_t)MROWS*CH];
__device__ bf16  g_ATl [(size_t)MROWS*CH];
__device__ bf16  g_Wqh[2*QKVN*CH], g_Wql[2*QKVN*CH];
__device__ bf16  g_Woh[2*CH*CH],   g_Wol[2*CH*CH];
__device__ bf16  g_Wph[CH*CH],     g_Wpl[CH*CH];

__device__ __forceinline__ void split_bf(float x, bf16& h, bf16& l) {
    h = __float2bfloat16(x);
    l = __float2bfloat16(x - __bfloat162float(h));
}

// ------------------------- transpose in -------------------------------------
__global__ void transpose_in(const float* __restrict__ x,
                             float* __restrict__ RES,
                             bf16* __restrict__ Yh, bf16* __restrict__ Yl) {
    __shared__ float tile[32][33];
    const int b  = blockIdx.z;
    const int t  = blockIdx.y >> 5;
    const int i  = blockIdx.y & 31;
    const int c0 = blockIdx.x << 5;
    const int tx = threadIdx.x, ty = threadIdx.y;   // (32,8)

    const float* xp = x + (((size_t)(b*CH + c0)*SEQ + t)*32 + i)*32;
#pragma unroll
    for (int r = 0; r < 4; r++) {
        int cl = ty + r*8;
        tile[cl][tx] = xp[(size_t)cl*SEQ*32*32 + tx];
    }
    __syncthreads();
#pragma unroll
    for (int r = 0; r < 4; r++) {
        int j = ty + r*8;
        size_t off = ((size_t)(b*1024 + i*32 + j)*SEQ + t)*CH + c0 + tx;
        float v = tile[tx][j];
        RES[off] = v;
        bf16 h, l; split_bf(v, h, l);
        Yh[off] = h; Yl[off] = l;
    }
}

// ------------------ transpose out + final mp_add ----------------------------
__global__ void transpose_out(const float* __restrict__ P,
                              const float* __restrict__ RES,
                              float* __restrict__ out) {
    __shared__ float tile[32][33];
    const int b  = blockIdx.z;
    const int t  = blockIdx.y >> 5;
    const int i  = blockIdx.y & 31;
    const int c0 = blockIdx.x << 5;
    const int tx = threadIdx.x, ty = threadIdx.y;

#pragma unroll
    for (int r = 0; r < 4; r++) {
        int j = ty + r*8;
        size_t off = ((size_t)(b*1024 + i*32 + j)*SEQ + t)*CH + c0 + tx;
        tile[tx][j] = (P[off]*0.7f + RES[off]*0.3f) * MP_INV;
    }
    __syncthreads();
    float* op = out + (((size_t)(b*CH + c0)*SEQ + t)*32 + i)*32;
#pragma unroll
    for (int r = 0; r < 4; r++) {
        int cl = ty + r*8;
        op[(size_t)cl*SEQ*32*32 + tx] = tile[cl][tx];
    }
}

// ----------------- weight row l2norm -> split bf16 --------------------------
__global__ void rownorm(const float* __restrict__ src,
                        bf16* __restrict__ dh, bf16* __restrict__ dl,
                        const float* __restrict__ gain) {
    const int row = blockIdx.x;
    const int t   = threadIdx.x;            // 128 threads, K=512
    const float4 v = ((const float4*)(src + (size_t)row*CH))[t];
    float ss = v.x*v.x + v.y*v.y + v.z*v.z + v.w*v.w;
#pragma unroll
    for (int o = 16; o; o >>= 1) ss += __shfl_xor_sync(0xffffffffu, ss, o);
    __shared__ float red[4];
    __shared__ float sscale;
    if ((t & 31) == 0) red[t >> 5] = ss;
    __syncthreads();
    if (t == 0) {
        float tot = red[0] + red[1] + red[2] + red[3];
        float sc = 1.f / (fmaxf(sqrtf(tot), 1e-4f) * 22.627416998f); // sqrt(512)
        if (gain) sc *= gain[0];
        sscale = sc;
    }
    __syncthreads();
    const float sc = sscale;
    float y[4] = {v.x*sc, v.y*sc, v.z*sc, v.w*sc};
    union { bf16 b[4]; uint2 u; } H, L;
#pragma unroll
    for (int i = 0; i < 4; i++) split_bf(y[i], H.b[i], L.b[i]);
    *(uint2*)(dh + (size_t)row*CH + 4*t) = H.u;
    *(uint2*)(dl + (size_t)row*CH + 4*t) = L.u;
}

// ==================== mma.sync split-bf16 GEMM (sm_80+ path) =================
// C[M,N] = A[M,512] @ B[N,512]^T  via  Ah·Bh + Ah·Bl + Al·Bh (fp32 accum).
// CTA tile 128x128, K-chunk 64 (128B rows, SW128), cp.async double buffer.
// 8 warps in 4(M) x 2(N); warp tile 32x64; mma m16n8k16.

#define TILE_B 16384               // one 128row x 128B tile
#define STAGE  (4*TILE_B)          // Ah, Al, Bh, Bl
#define GSMEM  (2*STAGE)           // 131072

__device__ __forceinline__ uint32_t sw128(uint32_t o) { return o ^ ((o >> 3) & 0x70); }

__device__ __forceinline__ void cp16(uint32_t dst, const void* src) {
    asm volatile("cp.async.cg.shared.global [%0], [%1], 16;\n" :: "r"(dst), "l"(src));
}
#define CP_COMMIT() asm volatile("cp.async.commit_group;\n" ::: "memory")
#define CP_WAIT(n)  asm volatile("cp.async.wait_group %0;\n" :: "n"(n) : "memory")

__device__ __forceinline__ void ldsm4(uint32_t (&r)[4], uint32_t addr) {
    asm volatile("ldmatrix.sync.aligned.m8n8.x4.shared.b16 {%0,%1,%2,%3}, [%4];"
                 : "=r"(r[0]), "=r"(r[1]), "=r"(r[2]), "=r"(r[3]) : "r"(addr));
}

__device__ __forceinline__ void mma16816(float (&d)[4], const uint32_t (&a)[4],
                                         const uint32_t* b) {
    asm volatile(
        "mma.sync.aligned.m16n8k16.row.col.f32.bf16.bf16.f32 "
        "{%0,%1,%2,%3}, {%4,%5,%6,%7}, {%8,%9}, {%0,%1,%2,%3};"
        : "+f"(d[0]), "+f"(d[1]), "+f"(d[2]), "+f"(d[3])
        : "r"(a[0]), "r"(a[1]), "r"(a[2]), "r"(a[3]), "r"(b[0]), "r"(b[1]));
}

template<int MODE>
__global__ void __launch_bounds__(256, 1)
gemm_mma(const bf16* __restrict__ Ah_, const bf16* __restrict__ Al_,
         const bf16* __restrict__ Bh_, const bf16* __restrict__ Bl_,
         float* __restrict__ C, bf16* __restrict__ Ch, bf16* __restrict__ Cl,
         int N) {
    extern __shared__ char smem[];
    const uint32_t sb = (uint32_t)__cvta_generic_to_shared(smem);
    const int tid   = threadIdx.x;
    const int lane  = tid & 31;
    const int warp  = tid >> 5;
    const int warpM = warp & 3;          // 0..3  -> 32-row slab
    const int warpN = warp >> 2;         // 0..1  -> 64-col slab
    const int m0 = blockIdx.y * 128;
    const int n0 = blockIdx.x * 128;

    float acc[2][8][4];
#pragma unroll
    for (int i = 0; i < 2; i++)
#pragma unroll
        for (int j = 0; j < 8; j++)
#pragma unroll
            for (int e = 0; e < 4; e++) acc[i][j][e] = 0.f;

    // ldmatrix lane addressing (within a 128B-row SW128 tile)
    const int a_row  = (lane & 15);              // + frag*16
    const int a_byte = (lane >> 4) << 4;         // + ks*32
    const int b_row  = (lane & 7) + ((lane >> 4) << 3);   // + group*16
    const int b_byte = ((lane >> 3) & 1) << 4;   // + ks*32

    // -------- chunk loader: 64 k-elements (128B) of all 4 tiles ------------
    auto load_chunk = [&](int c, int buf) {
        const uint32_t bb = sb + buf*STAGE;
        const int k0 = c * 64;
        for (int i = tid; i < 1024; i += 256) {      // 128 rows x 8 segs
            int r = i >> 3, s = i & 7;
            uint32_t o = sw128(r*128 + s*16);
            size_t ga = (size_t)(m0 + r)*CH + k0 + s*8;
            size_t gb = (size_t)(n0 + r)*CH + k0 + s*8;
            cp16(bb + o,            Ah_ + ga);
            cp16(bb + TILE_B   + o, Al_ + ga);
            cp16(bb + 2*TILE_B + o, Bh_ + gb);
            cp16(bb + 3*TILE_B + o, Bl_ + gb);
        }
        CP_COMMIT();
    };

    load_chunk(0, 0);

    for (int c = 0; c < 8; c++) {
        if (c + 1 < 8) load_chunk(c + 1, (c + 1) & 1);
        if (c + 1 < 8) { CP_WAIT(1); } else { CP_WAIT(0); }
        __syncthreads();

        const uint32_t bb = sb + (c & 1)*STAGE;
#pragma unroll
        for (int ks = 0; ks < 4; ks++) {
            const int kb = ks * 32;
            uint32_t ah[2][4], al[2][4];
#pragma unroll
            for (int mf = 0; mf < 2; mf++) {
                uint32_t ro = (uint32_t)(warpM*32 + mf*16 + a_row)*128 + kb + a_byte;
                ldsm4(ah[mf], bb + sw128(ro));
                ldsm4(al[mf], bb + TILE_B + sw128(ro));
            }
            uint32_t bh[8][2], bl[8][2];
#pragma unroll
            for (int g = 0; g < 4; g++) {
                uint32_t ro = (uint32_t)(warpN*64 + g*16 + b_row)*128 + kb + b_byte;
                uint32_t t[4];
                ldsm4(t, bb + 2*TILE_B + sw128(ro));
                bh[2*g][0] = t[0]; bh[2*g][1] = t[1];
                bh[2*g+1][0] = t[2]; bh[2*g+1][1] = t[3];
                ldsm4(t, bb + 3*TILE_B + sw128(ro));
                bl[2*g][0] = t[0]; bl[2*g][1] = t[1];
                bl[2*g+1][0] = t[2]; bl[2*g+1][1] = t[3];
            }
#pragma unroll
            for (int mf = 0; mf < 2; mf++)
#pragma unroll
                for (int nf = 0; nf < 8; nf++) {
                    mma16816(acc[mf][nf], ah[mf], bh[nf]);
                    mma16816(acc[mf][nf], ah[mf], bl[nf]);
                    mma16816(acc[mf][nf], al[mf], bh[nf]);
                }
        }
        __syncthreads();
    }

    // ------------------------------ epilogue --------------------------------
    const int mr = m0 + warpM*32 + (lane >> 2);
    const int nc = n0 + warpN*64 + (lane & 3)*2;
#pragma unroll
    for (int mf = 0; mf < 2; mf++)
#pragma unroll
        for (int nf = 0; nf < 8; nf++)
#pragma unroll
            for (int half = 0; half < 2; half++) {
                const int m = mr + mf*16 + half*8;
                const int n = nc + nf*8;
                float v0 = acc[mf][nf][half*2 + 0];
                float v1 = acc[mf][nf][half*2 + 1];
                float* Cp = C + (size_t)m*N + n;
                if (MODE == 0) {
                    *(float2*)Cp = make_float2(v0, v1);
                } else {
                    float2 old = *(const float2*)Cp;
                    v0 = (v0*0.7f + old.x*0.3f)*MP_INV;
                    v1 = (v1*0.7f + old.y*0.3f)*MP_INV;
                    *(float2*)Cp = make_float2(v0, v1);
                    union { bf16 b[2]; uint32_t u; } H, L;
                    split_bf(v0, H.b[0], L.b[0]);
                    split_bf(v1, H.b[1], L.b[1]);
                    *(uint32_t*)(Ch + (size_t)m*N + n) = H.u;
                    *(uint32_t*)(Cl + (size_t)m*N + n) = L.u;
                }
            }
}

// ------------------------- fused attention ----------------------------------
// 1 warp per (batch, head); outputs split-bf16 ATT directly.
__global__ void attention(const float* __restrict__ QKV,
                          const float* __restrict__ memkv,
                          bf16* __restrict__ Oh, bf16* __restrict__ Ol) {
    __shared__ float kn[KVLEN][DIMH];
    __shared__ float vn[KVLEN][DIMH];
    const int head = blockIdx.x;
    const int bt   = blockIdx.y;
    const int lane = threadIdx.x;
    const float* memk = memkv;
    const float* memv = memkv + HEADS*MEM*DIMH;

#pragma unroll
    for (int r = 0; r < KVLEN; r++) {
        const float* ks = (r < MEM)
            ? memk + ((size_t)head*MEM + r)*DIMH
            : QKV + ((size_t)bt*SEQ + (r-MEM))*QKVN + CH + head*DIMH;
        float x0 = ks[lane], x1 = ks[lane+32];
        float ss = x0*x0 + x1*x1;
#pragma unroll
        for (int o = 16; o; o >>= 1) ss += __shfl_xor_sync(0xffffffffu, ss, o);
        float s = 8.f / fmaxf(sqrtf(ss), 1e-4f);   // pixel_norm scale
        kn[r][lane] = x0*s; kn[r][lane+32] = x1*s;

        const float* vs = (r < MEM)
            ? memv + ((size_t)head*MEM + r)*DIMH
            : QKV + ((size_t)bt*SEQ + (r-MEM))*QKVN + 2*CH + head*DIMH;
        x0 = vs[lane]; x1 = vs[lane+32];
        ss = x0*x0 + x1*x1;
#pragma unroll
        for (int o = 16; o; o >>= 1) ss += __shfl_xor_sync(0xffffffffu, ss, o);
        s = 8.f / fmaxf(sqrtf(ss), 1e-4f);
        vn[r][lane] = x0*s; vn[r][lane+32] = x1*s;
    }
    __syncwarp();

    if (lane < SEQ) {
        const float4* qp = (const float4*)(QKV + ((size_t)bt*SEQ + lane)*QKVN + head*DIMH);
        float q[DIMH];
        float ss = 0.f;
#pragma unroll
        for (int d4 = 0; d4 < DIMH/4; d4++) {
            float4 v = qp[d4];
            q[4*d4+0]=v.x; q[4*d4+1]=v.y; q[4*d4+2]=v.z; q[4*d4+3]=v.w;
            ss += v.x*v.x + v.y*v.y + v.z*v.z + v.w*v.w;
        }
        const float qs = 1.f / fmaxf(sqrtf(ss), 1e-4f);

        float sc[KVLEN];
        float mx = -1e30f;
#pragma unroll
        for (int j = 0; j < KVLEN; j++) {
            float dot = 0.f;
#pragma unroll
            for (int d = 0; d < DIMH; d++) dot += q[d]*kn[j][d];
            dot *= qs;
            sc[j] = dot;
            mx = fmaxf(mx, dot);
        }
        float sum = 0.f;
#pragma unroll
        for (int j = 0; j < KVLEN; j++) { sc[j] = expf(sc[j] - mx); sum += sc[j]; }
        const float inv = 1.f / sum;

        float o[DIMH];
#pragma unroll
        for (int d = 0; d < DIMH; d++) o[d] = 0.f;
#pragma unroll
        for (int j = 0; j < KVLEN; j++) {
            float p = sc[j];
#pragma unroll
            for (int d = 0; d < DIMH; d++) o[d] += p * vn[j][d];
        }
        size_t base = ((size_t)bt*SEQ + lane)*CH + head*DIMH;
#pragma unroll
        for (int d4 = 0; d4 < DIMH/4; d4++) {
            union { bf16 b[4]; uint2 u; } H, L;
#pragma unroll
            for (int i = 0; i < 4; i++)
                split_bf(o[4*d4+i]*inv, H.b[i], L.b[i]);
            *(uint2*)(Oh + base + 4*d4) = H.u;
            *(uint2*)(Ol + base + 4*d4) = L.u;
        }
    }
}

// ------------------------------- launcher ------------------------------------
extern "C" void kernel_launch(void* const* d_in, const int* in_sizes, int n_in,
                              void* d_out, int out_size) {
    const float* x      = (const float*)d_in[0];
    const float* w_qkv  = (const float*)d_in[1];
    const float* w_out  = (const float*)d_in[2];
    const float* mem_kv = (const float*)d_in[3];
    const float* w_proj = (const float*)d_in[4];
    const float* gain   = (const float*)d_in[5];
    float* out = (float*)d_out;

    float *Y, *RES, *QKV;
    bf16 *Yh, *Yl, *ATh, *ATl, *Wqh, *Wql, *Woh, *Wol, *Wph, *Wpl;
    cudaGetSymbolAddress((void**)&Y,   g_Y);
    cudaGetSymbolAddress((void**)&RES, g_RES);
    cudaGetSymbolAddress((void**)&QKV, g_QKV);
    cudaGetSymbolAddress((void**)&Yh,  g_Yh);
    cudaGetSymbolAddress((void**)&Yl,  g_Yl);
    cudaGetSymbolAddress((void**)&ATh, g_ATh);
    cudaGetSymbolAddress((void**)&ATl, g_ATl);
    cudaGetSymbolAddress((void**)&Wqh, g_Wqh);
    cudaGetSymbolAddress((void**)&Wql, g_Wql);
    cudaGetSymbolAddress((void**)&Woh, g_Woh);
    cudaGetSymbolAddress((void**)&Wol, g_Wol);
    cudaGetSymbolAddress((void**)&Wph, g_Wph);
    cudaGetSymbolAddress((void**)&Wpl, g_Wpl);

    cudaFuncSetAttribute(gemm_mma<0>, cudaFuncAttributeMaxDynamicSharedMemorySize, GSMEM);
    cudaFuncSetAttribute(gemm_mma<1>, cudaFuncAttributeMaxDynamicSharedMemorySize, GSMEM);

    const dim3 tb(32, 8);
    const dim3 tg(16, 512, 2);

    transpose_in<<<tg, tb>>>(x, RES, Yh, Yl);

    rownorm<<<2*QKVN, 128>>>(w_qkv,  Wqh, Wql, nullptr);
    rownorm<<<2*CH,   128>>>(w_out,  Woh, Wol, nullptr);
    rownorm<<<CH,     128>>>(w_proj, Wph, Wpl, gain);

    // Y (fp32) must hold the attention-block input for the MODE-1 residual blend.
    cudaMemcpyAsync(Y, RES, (size_t)MROWS*CH*sizeof(float), cudaMemcpyDeviceToDevice);

    for (int l = 0; l < 2; l++) {
        gemm_mma<0><<<dim3(QKVN/128, MROWS/128), 256, GSMEM>>>(
            Yh, Yl, Wqh + (size_t)l*QKVN*CH, Wql + (size_t)l*QKVN*CH,
            QKV, nullptr, nullptr, QKVN);
        attention<<<dim3(HEADS, BATCH), 32>>>(
            QKV, mem_kv + (size_t)l*2*HEADS*MEM*DIMH, ATh, ATl);
        gemm_mma<1><<<dim3(CH/128, MROWS/128), 256, GSMEM>>>(
            ATh, ATl, Woh + (size_t)l*CH*CH, Wol + (size_t)l*CH*CH,
            Y, Yh, Yl, CH);
    }

    gemm_mma<0><<<dim3(CH/128, MROWS/128), 256, GSMEM>>>(
        Yh, Yl, Wph, Wpl, QKV, nullptr, nullptr, CH);
    transpose_out<<<tg, tb>>>(QKV, RES, out);
}

// round 7
// speedup vs baseline: 2.3086x; 1.0654x over previous
#include <cuda_runtime.h>
#include <cuda_fp16.h>
#include <math.h>
#include <stdint.h>

#define HEADS 8
#define DIMH  64
#define SEQ   16
#define CH    512
#define BATCH 2048              // b*h*w
#define MROWS (BATCH*SEQ)       // 32768
#define QKVN  1536
#define MEM   4
#define KVLEN 20
#define MP_INV 1.3130643286f    // 1/sqrt(0.58)

typedef __half f16;

// ------------------------- scratch (device globals) -------------------------
__device__ float g_Y   [(size_t)MROWS*CH];
__device__ float g_RES [(size_t)MROWS*CH];
__device__ float g_QKV [(size_t)MROWS*QKVN];
__device__ f16   g_Yh  [(size_t)MROWS*CH];
__device__ f16   g_Yl  [(size_t)MROWS*CH];
__device__ f16   g_ATh [(size_t)MROWS*CH];
__device__ f16   g_ATl [(size_t)MROWS*CH];
__device__ f16   g_Wq [2*QKVN*CH];
__device__ f16   g_Wo [2*CH*CH];
__device__ f16   g_Wp [CH*CH];

__device__ __forceinline__ void split_h(float x, f16& h, f16& l) {
    h = __float2half_rn(x);
    l = __float2half_rn(x - __half2float(h));
}

// ------------------------- transpose in -------------------------------------
__global__ void transpose_in(const float* __restrict__ x,
                             float* __restrict__ Y, float* __restrict__ RES,
                             f16* __restrict__ Yh, f16* __restrict__ Yl) {
    __shared__ float tile[32][33];
    const int b  = blockIdx.z;
    const int t  = blockIdx.y >> 5;
    const int i  = blockIdx.y & 31;
    const int c0 = blockIdx.x << 5;
    const int tx = threadIdx.x, ty = threadIdx.y;   // (32,8)

    const float* xp = x + (((size_t)(b*CH + c0)*SEQ + t)*32 + i)*32;
#pragma unroll
    for (int r = 0; r < 4; r++) {
        int cl = ty + r*8;
        tile[cl][tx] = xp[(size_t)cl*SEQ*32*32 + tx];
    }
    __syncthreads();
#pragma unroll
    for (int r = 0; r < 4; r++) {
        int j = ty + r*8;
        size_t off = ((size_t)(b*1024 + i*32 + j)*SEQ + t)*CH + c0 + tx;
        float v = tile[tx][j];
        Y[off] = v; RES[off] = v;
        f16 h, l; split_h(v, h, l);
        Yh[off] = h; Yl[off] = l;
    }
}

// ------------------ transpose out + final mp_add ----------------------------
__global__ void transpose_out(const float* __restrict__ P,
                              const float* __restrict__ RES,
                              float* __restrict__ out) {
    __shared__ float tile[32][33];
    const int b  = blockIdx.z;
    const int t  = blockIdx.y >> 5;
    const int i  = blockIdx.y & 31;
    const int c0 = blockIdx.x << 5;
    const int tx = threadIdx.x, ty = threadIdx.y;

#pragma unroll
    for (int r = 0; r < 4; r++) {
        int j = ty + r*8;
        size_t off = ((size_t)(b*1024 + i*32 + j)*SEQ + t)*CH + c0 + tx;
        tile[tx][j] = (P[off]*0.7f + RES[off]*0.3f) * MP_INV;
    }
    __syncthreads();
    float* op = out + (((size_t)(b*CH + c0)*SEQ + t)*32 + i)*32;
#pragma unroll
    for (int r = 0; r < 4; r++) {
        int cl = ty + r*8;
        op[(size_t)cl*SEQ*32*32 + tx] = tile[cl][tx];
    }
}

// ----------------- weight row l2norm -> fp16 --------------------------------
__global__ void rownorm(const float* __restrict__ src,
                        f16* __restrict__ dst,
                        const float* __restrict__ gain) {
    const int row = blockIdx.x;
    const int t   = threadIdx.x;            // 128 threads, K=512
    const float4 v = ((const float4*)(src + (size_t)row*CH))[t];
    float ss = v.x*v.x + v.y*v.y + v.z*v.z + v.w*v.w;
#pragma unroll
    for (int o = 16; o; o >>= 1) ss += __shfl_xor_sync(0xffffffffu, ss, o);
    __shared__ float red[4];
    __shared__ float sscale;
    if ((t & 31) == 0) red[t >> 5] = ss;
    __syncthreads();
    if (t == 0) {
        float tot = red[0] + red[1] + red[2] + red[3];
        float sc = 1.f / (fmaxf(sqrtf(tot), 1e-4f) * 22.627416998f); // sqrt(512)
        if (gain) sc *= gain[0];
        sscale = sc;
    }
    __syncthreads();
    const float sc = sscale;
    union { f16 b[4]; uint2 u; } H;
    H.b[0] = __float2half_rn(v.x*sc); H.b[1] = __float2half_rn(v.y*sc);
    H.b[2] = __float2half_rn(v.z*sc); H.b[3] = __float2half_rn(v.w*sc);
    *(uint2*)(dst + (size_t)row*CH + 4*t) = H.u;
}

// ==================== mma.sync split-fp16 GEMM ===============================
// C[M,N] = A[M,512] @ B[N,512]^T  via  Ah·B + Al·B (fp32 accum, B fp16-rounded).
// CTA tile 128x128, K-chunk 64 (128B rows, SW128), cp.async double buffer.
// 8 warps in 4(M) x 2(N); warp tile 32x64; mma m16n8k16 f16.

#define TILE_B 16384               // one 128row x 128B tile
#define STAGE  (3*TILE_B)          // Ah, Al, B
#define GSMEM  (2*STAGE)           // 98304

__device__ __forceinline__ uint32_t sw128(uint32_t o) { return o ^ ((o >> 3) & 0x70); }

__device__ __forceinline__ void cp16(uint32_t dst, const void* src) {
    asm volatile("cp.async.cg.shared.global [%0], [%1], 16;\n" :: "r"(dst), "l"(src));
}
#define CP_COMMIT() asm volatile("cp.async.commit_group;\n" ::: "memory")
#define CP_WAIT(n)  asm volatile("cp.async.wait_group %0;\n" :: "n"(n) : "memory")

__device__ __forceinline__ void ldsm4(uint32_t (&r)[4], uint32_t addr) {
    asm volatile("ldmatrix.sync.aligned.m8n8.x4.shared.b16 {%0,%1,%2,%3}, [%4];"
                 : "=r"(r[0]), "=r"(r[1]), "=r"(r[2]), "=r"(r[3]) : "r"(addr));
}

__device__ __forceinline__ void mma16816(float (&d)[4], const uint32_t (&a)[4],
                                         const uint32_t* b) {
    asm volatile(
        "mma.sync.aligned.m16n8k16.row.col.f32.f16.f16.f32 "
        "{%0,%1,%2,%3}, {%4,%5,%6,%7}, {%8,%9}, {%0,%1,%2,%3};"
        : "+f"(d[0]), "+f"(d[1]), "+f"(d[2]), "+f"(d[3])
        : "r"(a[0]), "r"(a[1]), "r"(a[2]), "r"(a[3]), "r"(b[0]), "r"(b[1]));
}

template<int MODE>
__global__ void __launch_bounds__(256, 1)
gemm_mma(const f16* __restrict__ Ah_, const f16* __restrict__ Al_,
         const f16* __restrict__ Bh_,
         float* __restrict__ C, f16* __restrict__ Ch, f16* __restrict__ Cl,
         int N) {
    extern __shared__ char smem[];
    const uint32_t sb = (uint32_t)__cvta_generic_to_shared(smem);
    const int tid   = threadIdx.x;
    const int lane  = tid & 31;
    const int warp  = tid >> 5;
    const int warpM = warp & 3;          // 0..3  -> 32-row slab
    const int warpN = warp >> 2;         // 0..1  -> 64-col slab
    const int m0 = blockIdx.y * 128;
    const int n0 = blockIdx.x * 128;

    float acc[2][8][4];
#pragma unroll
    for (int i = 0; i < 2; i++)
#pragma unroll
        for (int j = 0; j < 8; j++)
#pragma unroll
            for (int e = 0; e < 4; e++) acc[i][j][e] = 0.f;

    // ldmatrix lane addressing (within a 128B-row SW128 tile)
    const int a_row  = (lane & 15);              // + frag*16
    const int a_byte = (lane >> 4) << 4;         // + ks*32
    const int b_row  = (lane & 7) + ((lane >> 4) << 3);   // + group*16
    const int b_byte = ((lane >> 3) & 1) << 4;   // + ks*32

    // -------- chunk loader: 64 k-elements (128B rows) of all 3 tiles --------
    auto load_chunk = [&](int c, int buf) {
        const uint32_t bb = sb + buf*STAGE;
        const int k0 = c * 64;
#pragma unroll
        for (int i = tid; i < 1024; i += 256) {      // 128 rows x 8 segs
            int r = i >> 3, s = i & 7;
            uint32_t o = sw128(r*128 + s*16);
            size_t ga = (size_t)(m0 + r)*CH + k0 + s*8;
            size_t gb = (size_t)(n0 + r)*CH + k0 + s*8;
            cp16(bb + o,            Ah_ + ga);
            cp16(bb + TILE_B   + o, Al_ + ga);
            cp16(bb + 2*TILE_B + o, Bh_ + gb);
        }
        CP_COMMIT();
    };

    load_chunk(0, 0);

    for (int c = 0; c < 8; c++) {
        if (c + 1 < 8) load_chunk(c + 1, (c + 1) & 1);
        if (c + 1 < 8) { CP_WAIT(1); } else { CP_WAIT(0); }
        __syncthreads();

        const uint32_t bb = sb + (c & 1)*STAGE;
#pragma unroll
        for (int ks = 0; ks < 4; ks++) {
            const int kb = ks * 32;
            uint32_t ah[2][4], al[2][4];
#pragma unroll
            for (int mf = 0; mf < 2; mf++) {
                uint32_t ro = (uint32_t)(warpM*32 + mf*16 + a_row)*128 + kb + a_byte;
                ldsm4(ah[mf], bb + sw128(ro));
                ldsm4(al[mf], bb + TILE_B + sw128(ro));
            }
            uint32_t bh[8][2];
#pragma unroll
            for (int g = 0; g < 4; g++) {
                uint32_t ro = (uint32_t)(warpN*64 + g*16 + b_row)*128 + kb + b_byte;
                uint32_t t[4];
                ldsm4(t, bb + 2*TILE_B + sw128(ro));
                bh[2*g][0] = t[0]; bh[2*g][1] = t[1];
                bh[2*g+1][0] = t[2]; bh[2*g+1][1] = t[3];
            }
#pragma unroll
            for (int mf = 0; mf < 2; mf++)
#pragma unroll
                for (int nf = 0; nf < 8; nf++) {
                    mma16816(acc[mf][nf], ah[mf], bh[nf]);
                    mma16816(acc[mf][nf], al[mf], bh[nf]);
                }
        }
        __syncthreads();
    }

    // ------------------------------ epilogue --------------------------------
    const int mr = m0 + warpM*32 + (lane >> 2);
    const int nc = n0 + warpN*64 + (lane & 3)*2;
#pragma unroll
    for (int mf = 0; mf < 2; mf++)
#pragma unroll
        for (int nf = 0; nf < 8; nf++)
#pragma unroll
            for (int half = 0; half < 2; half++) {
                const int m = mr + mf*16 + half*8;
                const int n = nc + nf*8;
                float v0 = acc[mf][nf][half*2 + 0];
                float v1 = acc[mf][nf][half*2 + 1];
                float* Cp = C + (size_t)m*N + n;
                if (MODE == 0) {
                    *(float2*)Cp = make_float2(v0, v1);
                } else {
                    float2 old = *(const float2*)Cp;
                    v0 = (v0*0.7f + old.x*0.3f)*MP_INV;
                    v1 = (v1*0.7f + old.y*0.3f)*MP_INV;
                    *(float2*)Cp = make_float2(v0, v1);
                    union { f16 b[2]; uint32_t u; } H, L;
                    split_h(v0, H.b[0], L.b[0]);
                    split_h(v1, H.b[1], L.b[1]);
                    *(uint32_t*)(Ch + (size_t)m*N + n) = H.u;
                    *(uint32_t*)(Cl + (size_t)m*N + n) = L.u;
                }
            }
}

// ------------------------- fused attention ----------------------------------
// 1 warp per (batch, head-pair): lanes 0-15 handle head hp, 16-31 head hp+1.
__global__ void attention(const float* __restrict__ QKV,
                          const float* __restrict__ memkv,
                          f16* __restrict__ Oh, f16* __restrict__ Ol) {
    __shared__ float kn[2][KVLEN][DIMH];
    __shared__ float vn[2][KVLEN][DIMH];
    const int hp   = blockIdx.x << 1;
    const int bt   = blockIdx.y;
    const int lane = threadIdx.x;
    const float* memk = memkv;
    const float* memv = memkv + HEADS*MEM*DIMH;

#pragma unroll
    for (int idx = 0; idx < 2*KVLEN; idx++) {
        const int hh = idx / KVLEN;
        const int r  = idx % KVLEN;
        const int head = hp + hh;
        const float* ks = (r < MEM)
            ? memk + ((size_t)head*MEM + r)*DIMH
            : QKV + ((size_t)bt*SEQ + (r-MEM))*QKVN + CH + head*DIMH;
        float x0 = ks[lane], x1 = ks[lane+32];
        float ss = x0*x0 + x1*x1;
#pragma unroll
        for (int o = 16; o; o >>= 1) ss += __shfl_xor_sync(0xffffffffu, ss, o);
        float s = 8.f / fmaxf(sqrtf(ss), 1e-4f);   // pixel_norm scale
        kn[hh][r][lane] = x0*s; kn[hh][r][lane+32] = x1*s;

        const float* vs = (r < MEM)
            ? memv + ((size_t)head*MEM + r)*DIMH
            : QKV + ((size_t)bt*SEQ + (r-MEM))*QKVN + 2*CH + head*DIMH;
        x0 = vs[lane]; x1 = vs[lane+32];
        ss = x0*x0 + x1*x1;
#pragma unroll
        for (int o = 16; o; o >>= 1) ss += __shfl_xor_sync(0xffffffffu, ss, o);
        s = 8.f / fmaxf(sqrtf(ss), 1e-4f);
        vn[hh][r][lane] = x0*s; vn[hh][r][lane+32] = x1*s;
    }
    __syncwarp();

    // lanes 0-15: head hp, rows 0-15; lanes 16-31: head hp+1, rows 0-15
    const int hh  = lane >> 4;
    const int row = lane & 15;
    const int head = hp + hh;

    const float4* qp = (const float4*)(QKV + ((size_t)bt*SEQ + row)*QKVN + head*DIMH);
    float q[DIMH];
    float ss = 0.f;
#pragma unroll
    for (int d4 = 0; d4 < DIMH/4; d4++) {
        float4 v = qp[d4];
        q[4*d4+0]=v.x; q[4*d4+1]=v.y; q[4*d4+2]=v.z; q[4*d4+3]=v.w;
        ss += v.x*v.x + v.y*v.y + v.z*v.z + v.w*v.w;
    }
    const float qs = 1.f / fmaxf(sqrtf(ss), 1e-4f);  // pixel_norm(q)*D^-1/2 == l2norm

    float sc[KVLEN];
    float mx = -1e30f;
#pragma unroll
    for (int j = 0; j < KVLEN; j++) {
        float dot = 0.f;
#pragma unroll
        for (int d = 0; d < DIMH; d++) dot += q[d]*kn[hh][j][d];
        dot *= qs;
        sc[j] = dot;
        mx = fmaxf(mx, dot);
    }
    float sum = 0.f;
#pragma unroll
    for (int j = 0; j < KVLEN; j++) { sc[j] = expf(sc[j] - mx); sum += sc[j]; }
    const float inv = 1.f / sum;

    float o[DIMH];
#pragma unroll
    for (int d = 0; d < DIMH; d++) o[d] = 0.f;
#pragma unroll
    for (int j = 0; j < KVLEN; j++) {
        float p = sc[j];
#pragma unroll
        for (int d = 0; d < DIMH; d++) o[d] += p * vn[hh][j][d];
    }
    size_t base = ((size_t)bt*SEQ + row)*CH + head*DIMH;
#pragma unroll
    for (int d4 = 0; d4 < DIMH/4; d4++) {
        union { f16 b[4]; uint2 u; } H, L;
#pragma unroll
        for (int i = 0; i < 4; i++)
            split_h(o[4*d4+i]*inv, H.b[i], L.b[i]);
        *(uint2*)(Oh + base + 4*d4) = H.u;
        *(uint2*)(Ol + base + 4*d4) = L.u;
    }
}

// ------------------------------- launcher ------------------------------------
extern "C" void kernel_launch(void* const* d_in, const int* in_sizes, int n_in,
                              void* d_out, int out_size) {
    const float* x      = (const float*)d_in[0];
    const float* w_qkv  = (const float*)d_in[1];
    const float* w_out  = (const float*)d_in[2];
    const float* mem_kv = (const float*)d_in[3];
    const float* w_proj = (const float*)d_in[4];
    const float* gain   = (const float*)d_in[5];
    float* out = (float*)d_out;

    float *Y, *RES, *QKV;
    f16 *Yh, *Yl, *ATh, *ATl, *Wq, *Wo, *Wp;
    cudaGetSymbolAddress((void**)&Y,   g_Y);
    cudaGetSymbolAddress((void**)&RES, g_RES);
    cudaGetSymbolAddress((void**)&QKV, g_QKV);
    cudaGetSymbolAddress((void**)&Yh,  g_Yh);
    cudaGetSymbolAddress((void**)&Yl,  g_Yl);
    cudaGetSymbolAddress((void**)&ATh, g_ATh);
    cudaGetSymbolAddress((void**)&ATl, g_ATl);
    cudaGetSymbolAddress((void**)&Wq,  g_Wq);
    cudaGetSymbolAddress((void**)&Wo,  g_Wo);
    cudaGetSymbolAddress((void**)&Wp,  g_Wp);

    cudaFuncSetAttribute(gemm_mma<0>, cudaFuncAttributeMaxDynamicSharedMemorySize, GSMEM);
    cudaFuncSetAttribute(gemm_mma<1>, cudaFuncAttributeMaxDynamicSharedMemorySize, GSMEM);

    const dim3 tb(32, 8);
    const dim3 tg(16, 512, 2);

    transpose_in<<<tg, tb>>>(x, Y, RES, Yh, Yl);

    rownorm<<<2*QKVN, 128>>>(w_qkv,  Wq, nullptr);
    rownorm<<<2*CH,   128>>>(w_out,  Wo, nullptr);
    rownorm<<<CH,     128>>>(w_proj, Wp, gain);

    for (int l = 0; l < 2; l++) {
        gemm_mma<0><<<dim3(QKVN/128, MROWS/128), 256, GSMEM>>>(
            Yh, Yl, Wq + (size_t)l*QKVN*CH,
            QKV, nullptr, nullptr, QKVN);
        attention<<<dim3(HEADS/2, BATCH), 32>>>(
            QKV, mem_kv + (size_t)l*2*HEADS*MEM*DIMH, ATh, ATl);
        gemm_mma<1><<<dim3(CH/128, MROWS/128), 256, GSMEM>>>(
            ATh, ATl, Wo + (size_t)l*CH*CH,
            Y, Yh, Yl, CH);
    }

    gemm_mma<0><<<dim3(CH/128, MROWS/128), 256, GSMEM>>>(
        Yh, Yl, Wp, QKV, nullptr, nullptr, CH);
    transpose_out<<<tg, tb>>>(QKV, RES, out);
}

// round 9
// speedup vs baseline: 2.5796x; 1.1174x over previous
#include <cuda_runtime.h>
#include <cuda_fp16.h>
#include <math.h>
#include <stdint.h>

#define HEADS 8
#define DIMH  64
#define SEQ   16
#define CH    512
#define BATCH 2048              // b*h*w
#define MROWS (BATCH*SEQ)       // 32768
#define QKVN  1536
#define MEM   4
#define KVLEN 20
#define MP_INV 1.3130643286f    // 1/sqrt(0.58)

typedef __half f16;

// ------------------------- scratch (device globals) -------------------------
__device__ float g_Y   [(size_t)MROWS*CH];
__device__ float g_RES [(size_t)MROWS*CH];
__device__ float g_QKV [(size_t)MROWS*QKVN];
__device__ f16   g_Yh  [(size_t)MROWS*CH];
__device__ f16   g_Yl  [(size_t)MROWS*CH];
__device__ f16   g_ATh [(size_t)MROWS*CH];
__device__ f16   g_ATl [(size_t)MROWS*CH];
__device__ f16   g_Wq [2*QKVN*CH];
__device__ f16   g_Wo [2*CH*CH];
__device__ f16   g_Wp [CH*CH];

__device__ __forceinline__ void split_h(float x, f16& h, f16& l) {
    h = __float2half_rn(x);
    l = __float2half_rn(x - __half2float(h));
}

// ------------------------- transpose in -------------------------------------
__global__ void transpose_in(const float* __restrict__ x,
                             float* __restrict__ Y, float* __restrict__ RES,
                             f16* __restrict__ Yh, f16* __restrict__ Yl) {
    __shared__ float tile[32][33];
    const int b  = blockIdx.z;
    const int t  = blockIdx.y >> 5;
    const int i  = blockIdx.y & 31;
    const int c0 = blockIdx.x << 5;
    const int tx = threadIdx.x, ty = threadIdx.y;   // (32,8)

    const float* xp = x + (((size_t)(b*CH + c0)*SEQ + t)*32 + i)*32;
#pragma unroll
    for (int r = 0; r < 4; r++) {
        int cl = ty + r*8;
        tile[cl][tx] = xp[(size_t)cl*SEQ*32*32 + tx];
    }
    __syncthreads();
#pragma unroll
    for (int r = 0; r < 4; r++) {
        int j = ty + r*8;
        size_t off = ((size_t)(b*1024 + i*32 + j)*SEQ + t)*CH + c0 + tx;
        float v = tile[tx][j];
        Y[off] = v; RES[off] = v;
        f16 h, l; split_h(v, h, l);
        Yh[off] = h; Yl[off] = l;
    }
}

// ------------------ transpose out + final mp_add ----------------------------
__global__ void transpose_out(const float* __restrict__ P,
                              const float* __restrict__ RES,
                              float* __restrict__ out) {
    __shared__ float tile[32][33];
    const int b  = blockIdx.z;
    const int t  = blockIdx.y >> 5;
    const int i  = blockIdx.y & 31;
    const int c0 = blockIdx.x << 5;
    const int tx = threadIdx.x, ty = threadIdx.y;

#pragma unroll
    for (int r = 0; r < 4; r++) {
        int j = ty + r*8;
        size_t off = ((size_t)(b*1024 + i*32 + j)*SEQ + t)*CH + c0 + tx;
        tile[tx][j] = (P[off]*0.7f + RES[off]*0.3f) * MP_INV;
    }
    __syncthreads();
    float* op = out + (((size_t)(b*CH + c0)*SEQ + t)*32 + i)*32;
#pragma unroll
    for (int r = 0; r < 4; r++) {
        int cl = ty + r*8;
        op[(size_t)cl*SEQ*32*32 + tx] = tile[cl][tx];
    }
}

// ----------------- weight row l2norm -> fp16 --------------------------------
__global__ void rownorm(const float* __restrict__ src,
                        f16* __restrict__ dst,
                        const float* __restrict__ gain) {
    const int row = blockIdx.x;
    const int t   = threadIdx.x;            // 128 threads, K=512
    const float4 v = ((const float4*)(src + (size_t)row*CH))[t];
    float ss = v.x*v.x + v.y*v.y + v.z*v.z + v.w*v.w;
#pragma unroll
    for (int o = 16; o; o >>= 1) ss += __shfl_xor_sync(0xffffffffu, ss, o);
    __shared__ float red[4];
    __shared__ float sscale;
    if ((t & 31) == 0) red[t >> 5] = ss;
    __syncthreads();
    if (t == 0) {
        float tot = red[0] + red[1] + red[2] + red[3];
        float sc = 1.f / (fmaxf(sqrtf(tot), 1e-4f) * 22.627416998f); // sqrt(512)
        if (gain) sc *= gain[0];
        sscale = sc;
    }
    __syncthreads();
    const float sc = sscale;
    union { f16 b[4]; uint2 u; } H;
    H.b[0] = __float2half_rn(v.x*sc); H.b[1] = __float2half_rn(v.y*sc);
    H.b[2] = __float2half_rn(v.z*sc); H.b[3] = __float2half_rn(v.w*sc);
    *(uint2*)(dst + (size_t)row*CH + 4*t) = H.u;
}

// ==================== mma.sync split-fp16 GEMM ===============================
// C[M,N] = A[M,512] @ B[N,512]^T  via  Ah·B + Al·B (fp32 accum, B fp16-rounded).
// CTA tile 128x128, K-chunk 64 (128B rows, SW128), cp.async double buffer.
// 8 warps in 4(M) x 2(N); warp tile 32x64; mma m16n8k16 f16. 2 CTAs/SM.

#define TILE_B 16384               // one 128row x 128B tile
#define STAGE  (3*TILE_B)          // Ah, Al, B
#define GSMEM  (2*STAGE)           // 98304

__device__ __forceinline__ uint32_t sw128(uint32_t o) { return o ^ ((o >> 3) & 0x70); }

__device__ __forceinline__ void cp16(uint32_t dst, const void* src) {
    asm volatile("cp.async.cg.shared.global [%0], [%1], 16;\n" :: "r"(dst), "l"(src));
}
#define CP_COMMIT() asm volatile("cp.async.commit_group;\n" ::: "memory")
#define CP_WAIT(n)  asm volatile("cp.async.wait_group %0;\n" :: "n"(n) : "memory")

__device__ __forceinline__ void ldsm4(uint32_t (&r)[4], uint32_t addr) {
    asm volatile("ldmatrix.sync.aligned.m8n8.x4.shared.b16 {%0,%1,%2,%3}, [%4];"
                 : "=r"(r[0]), "=r"(r[1]), "=r"(r[2]), "=r"(r[3]) : "r"(addr));
}

__device__ __forceinline__ void mma16816(float (&d)[4], const uint32_t (&a)[4],
                                         const uint32_t* b) {
    asm volatile(
        "mma.sync.aligned.m16n8k16.row.col.f32.f16.f16.f32 "
        "{%0,%1,%2,%3}, {%4,%5,%6,%7}, {%8,%9}, {%0,%1,%2,%3};"
        : "+f"(d[0]), "+f"(d[1]), "+f"(d[2]), "+f"(d[3])
        : "r"(a[0]), "r"(a[1]), "r"(a[2]), "r"(a[3]), "r"(b[0]), "r"(b[1]));
}

template<int MODE>
__global__ void __launch_bounds__(256, 2)
gemm_mma(const f16* __restrict__ Ah_, const f16* __restrict__ Al_,
         const f16* __restrict__ Bh_,
         float* __restrict__ C, f16* __restrict__ Ch, f16* __restrict__ Cl,
         int N) {
    extern __shared__ char smem[];
    const uint32_t sb = (uint32_t)__cvta_generic_to_shared(smem);
    const int tid   = threadIdx.x;
    const int lane  = tid & 31;
    const int warp  = tid >> 5;
    const int warpM = warp & 3;          // 0..3  -> 32-row slab
    const int warpN = warp >> 2;         // 0..1  -> 64-col slab
    const int m0 = blockIdx.y * 128;
    const int n0 = blockIdx.x * 128;

    float acc[2][8][4];
#pragma unroll
    for (int i = 0; i < 2; i++)
#pragma unroll
        for (int j = 0; j < 8; j++)
#pragma unroll
            for (int e = 0; e < 4; e++) acc[i][j][e] = 0.f;

    // ldmatrix lane addressing (within a 128B-row SW128 tile)
    const int a_row  = (lane & 15);              // + frag*16
    const int a_byte = (lane >> 4) << 4;         // + ks*32
    const int b_row  = (lane & 7) + ((lane >> 4) << 3);   // + group*16
    const int b_byte = ((lane >> 3) & 1) << 4;   // + ks*32

    // -------- chunk loader: 64 k-elements (128B rows) of all 3 tiles --------
    auto load_chunk = [&](int c, int buf) {
        const uint32_t bb = sb + buf*STAGE;
        const int k0 = c * 64;
#pragma unroll
        for (int i = tid; i < 1024; i += 256) {      // 128 rows x 8 segs
            int r = i >> 3, s = i & 7;
            uint32_t o = sw128(r*128 + s*16);
            size_t ga = (size_t)(m0 + r)*CH + k0 + s*8;
            size_t gb = (size_t)(n0 + r)*CH + k0 + s*8;
            cp16(bb + o,            Ah_ + ga);
            cp16(bb + TILE_B   + o, Al_ + ga);
            cp16(bb + 2*TILE_B + o, Bh_ + gb);
        }
        CP_COMMIT();
    };

    load_chunk(0, 0);

    for (int c = 0; c < 8; c++) {
        if (c + 1 < 8) load_chunk(c + 1, (c + 1) & 1);
        if (c + 1 < 8) { CP_WAIT(1); } else { CP_WAIT(0); }
        __syncthreads();

        const uint32_t bb = sb + (c & 1)*STAGE;
#pragma unroll
        for (int ks = 0; ks < 4; ks++) {
            const int kb = ks * 32;
            uint32_t ah[2][4], al[2][4];
#pragma unroll
            for (int mf = 0; mf < 2; mf++) {
                uint32_t ro = (uint32_t)(warpM*32 + mf*16 + a_row)*128 + kb + a_byte;
                ldsm4(ah[mf], bb + sw128(ro));
                ldsm4(al[mf], bb + TILE_B + sw128(ro));
            }
            uint32_t bh[8][2];
#pragma unroll
            for (int g = 0; g < 4; g++) {
                uint32_t ro = (uint32_t)(warpN*64 + g*16 + b_row)*128 + kb + b_byte;
                uint32_t t[4];
                ldsm4(t, bb + 2*TILE_B + sw128(ro));
                bh[2*g][0] = t[0]; bh[2*g][1] = t[1];
                bh[2*g+1][0] = t[2]; bh[2*g+1][1] = t[3];
            }
#pragma unroll
            for (int mf = 0; mf < 2; mf++)
#pragma unroll
                for (int nf = 0; nf < 8; nf++) {
                    mma16816(acc[mf][nf], ah[mf], bh[nf]);
                    mma16816(acc[mf][nf], al[mf], bh[nf]);
                }
        }
        __syncthreads();
    }

    // ------------------------------ epilogue --------------------------------
    const int mr = m0 + warpM*32 + (lane >> 2);
    const int nc = n0 + warpN*64 + (lane & 3)*2;
#pragma unroll
    for (int mf = 0; mf < 2; mf++)
#pragma unroll
        for (int nf = 0; nf < 8; nf++)
#pragma unroll
            for (int half = 0; half < 2; half++) {
                const int m = mr + mf*16 + half*8;
                const int n = nc + nf*8;
                float v0 = acc[mf][nf][half*2 + 0];
                float v1 = acc[mf][nf][half*2 + 1];
                float* Cp = C + (size_t)m*N + n;
                if (MODE == 0) {
                    *(float2*)Cp = make_float2(v0, v1);
                } else {
                    float2 old = *(const float2*)Cp;
                    v0 = (v0*0.7f + old.x*0.3f)*MP_INV;
                    v1 = (v1*0.7f + old.y*0.3f)*MP_INV;
                    *(float2*)Cp = make_float2(v0, v1);
                    union { f16 b[2]; uint32_t u; } H, L;
                    split_h(v0, H.b[0], L.b[0]);
                    split_h(v1, H.b[1], L.b[1]);
                    *(uint32_t*)(Ch + (size_t)m*N + n) = H.u;
                    *(uint32_t*)(Cl + (size_t)m*N + n) = L.u;
                }
            }
}

// ------------------------- fused attention ----------------------------------
// 1 warp per (batch, head-pair): lanes 0-15 handle head hp, 16-31 head hp+1.
__global__ void attention(const float* __restrict__ QKV,
                          const float* __restrict__ memkv,
                          f16* __restrict__ Oh, f16* __restrict__ Ol) {
    __shared__ float kn[2][KVLEN][DIMH];
    __shared__ float vn[2][KVLEN][DIMH];
    const int hp   = blockIdx.x << 1;
    const int bt   = blockIdx.y;
    const int lane = threadIdx.x;
    const float* memk = memkv;
    const float* memv = memkv + HEADS*MEM*DIMH;

#pragma unroll
    for (int idx = 0; idx < 2*KVLEN; idx++) {
        const int hh = idx / KVLEN;
        const int r  = idx % KVLEN;
        const int head = hp + hh;
        const float* ks = (r < MEM)
            ? memk + ((size_t)head*MEM + r)*DIMH
            : QKV + ((size_t)bt*SEQ + (r-MEM))*QKVN + CH + head*DIMH;
        float x0 = ks[lane], x1 = ks[lane+32];
        float ss = x0*x0 + x1*x1;
#pragma unroll
        for (int o = 16; o; o >>= 1) ss += __shfl_xor_sync(0xffffffffu, ss, o);
        float s = 8.f / fmaxf(sqrtf(ss), 1e-4f);   // pixel_norm scale
        kn[hh][r][lane] = x0*s; kn[hh][r][lane+32] = x1*s;

        const float* vs = (r < MEM)
            ? memv + ((size_t)head*MEM + r)*DIMH
            : QKV + ((size_t)bt*SEQ + (r-MEM))*QKVN + 2*CH + head*DIMH;
        x0 = vs[lane]; x1 = vs[lane+32];
        ss = x0*x0 + x1*x1;
#pragma unroll
        for (int o = 16; o; o >>= 1) ss += __shfl_xor_sync(0xffffffffu, ss, o);
        s = 8.f / fmaxf(sqrtf(ss), 1e-4f);
        vn[hh][r][lane] = x0*s; vn[hh][r][lane+32] = x1*s;
    }
    __syncwarp();

    // lanes 0-15: head hp, rows 0-15; lanes 16-31: head hp+1, rows 0-15
    const int hh  = lane >> 4;
    const int row = lane & 15;
    const int head = hp + hh;

    const float4* qp = (const float4*)(QKV + ((size_t)bt*SEQ + row)*QKVN + head*DIMH);
    float q[DIMH];
    float ss = 0.f;
#pragma unroll
    for (int d4 = 0; d4 < DIMH/4; d4++) {
        float4 v = qp[d4];
        q[4*d4+0]=v.x; q[4*d4+1]=v.y; q[4*d4+2]=v.z; q[4*d4+3]=v.w;
        ss += v.x*v.x + v.y*v.y + v.z*v.z + v.w*v.w;
    }
    const float qs = 1.f / fmaxf(sqrtf(ss), 1e-4f);  // pixel_norm(q)*D^-1/2 == l2norm

    float sc[KVLEN];
    float mx = -1e30f;
#pragma unroll
    for (int j = 0; j < KVLEN; j++) {
        float dot = 0.f;
#pragma unroll
        for (int d = 0; d < DIMH; d++) dot += q[d]*kn[hh][j][d];
        dot *= qs;
        sc[j] = dot;
        mx = fmaxf(mx, dot);
    }
    float sum = 0.f;
#pragma unroll
    for (int j = 0; j < KVLEN; j++) { sc[j] = expf(sc[j] - mx); sum += sc[j]; }
    const float inv = 1.f / sum;

    float o[DIMH];
#pragma unroll
    for (int d = 0; d < DIMH; d++) o[d] = 0.f;
#pragma unroll
    for (int j = 0; j < KVLEN; j++) {
        float p = sc[j];
#pragma unroll
        for (int d = 0; d < DIMH; d++) o[d] += p * vn[hh][j][d];
    }
    size_t base = ((size_t)bt*SEQ + row)*CH + head*DIMH;
#pragma unroll
    for (int d4 = 0; d4 < DIMH/4; d4++) {
        union { f16 b[4]; uint2 u; } H, L;
#pragma unroll
        for (int i = 0; i < 4; i++)
            split_h(o[4*d4+i]*inv, H.b[i], L.b[i]);
        *(uint2*)(Oh + base + 4*d4) = H.u;
        *(uint2*)(Ol + base + 4*d4) = L.u;
    }
}

// ------------------------------- launcher ------------------------------------
extern "C" void kernel_launch(void* const* d_in, const int* in_sizes, int n_in,
                              void* d_out, int out_size) {
    const float* x      = (const float*)d_in[0];
    const float* w_qkv  = (const float*)d_in[1];
    const float* w_out  = (const float*)d_in[2];
    const float* mem_kv = (const float*)d_in[3];
    const float* w_proj = (const float*)d_in[4];
    const float* gain   = (const float*)d_in[5];
    float* out = (float*)d_out;

    float *Y, *RES, *QKV;
    f16 *Yh, *Yl, *ATh, *ATl, *Wq, *Wo, *Wp;
    cudaGetSymbolAddress((void**)&Y,   g_Y);
    cudaGetSymbolAddress((void**)&RES, g_RES);
    cudaGetSymbolAddress((void**)&QKV, g_QKV);
    cudaGetSymbolAddress((void**)&Yh,  g_Yh);
    cudaGetSymbolAddress((void**)&Yl,  g_Yl);
    cudaGetSymbolAddress((void**)&ATh, g_ATh);
    cudaGetSymbolAddress((void**)&ATl, g_ATl);
    cudaGetSymbolAddress((void**)&Wq,  g_Wq);
    cudaGetSymbolAddress((void**)&Wo,  g_Wo);
    cudaGetSymbolAddress((void**)&Wp,  g_Wp);

    cudaFuncSetAttribute(gemm_mma<0>, cudaFuncAttributeMaxDynamicSharedMemorySize, GSMEM);
    cudaFuncSetAttribute(gemm_mma<1>, cudaFuncAttributeMaxDynamicSharedMemorySize, GSMEM);

    const dim3 tb(32, 8);
    const dim3 tg(16, 512, 2);

    transpose_in<<<tg, tb>>>(x, Y, RES, Yh, Yl);

    rownorm<<<2*QKVN, 128>>>(w_qkv,  Wq, nullptr);
    rownorm<<<2*CH,   128>>>(w_out,  Wo, nullptr);
    rownorm<<<CH,     128>>>(w_proj, Wp, gain);

    for (int l = 0; l < 2; l++) {
        gemm_mma<0><<<dim3(QKVN/128, MROWS/128), 256, GSMEM>>>(
            Yh, Yl, Wq + (size_t)l*QKVN*CH,
            QKV, nullptr, nullptr, QKVN);
        attention<<<dim3(HEADS/2, BATCH), 32>>>(
            QKV, mem_kv + (size_t)l*2*HEADS*MEM*DIMH, ATh, ATl);
        gemm_mma<1><<<dim3(CH/128, MROWS/128), 256, GSMEM>>>(
            ATh, ATl, Wo + (size_t)l*CH*CH,
            Y, Yh, Yl, CH);
    }

    gemm_mma<0><<<dim3(CH/128, MROWS/128), 256, GSMEM>>>(
        Yh, Yl, Wp, QKV, nullptr, nullptr, CH);
    transpose_out<<<tg, tb>>>(QKV, RES, out);
}

// round 10
// speedup vs baseline: 3.2276x; 1.2512x over previous
#include <cuda_runtime.h>
#include <cuda_fp16.h>
#include <math.h>
#include <stdint.h>

#define HEADS 8
#define DIMH  64
#define SEQ   16
#define CH    512
#define BATCH 2048              // b*h*w
#define MROWS (BATCH*SEQ)       // 32768
#define QKVN  1536
#define MEM   4
#define KVLEN 20
#define MP_INV 1.3130643286f    // 1/sqrt(0.58)

typedef __half f16;

// ------------------------- scratch (device globals) -------------------------
__device__ float g_Y   [(size_t)MROWS*CH];
__device__ float g_RES [(size_t)MROWS*CH];
__device__ float g_QKV [(size_t)MROWS*QKVN];
__device__ f16   g_Yh  [(size_t)MROWS*CH];
__device__ f16   g_ATh [(size_t)MROWS*CH];
__device__ f16   g_Wq [2*QKVN*CH];
__device__ f16   g_Wo [2*CH*CH];
__device__ f16   g_Wp [CH*CH];

// ------------------------- transpose in -------------------------------------
__global__ void transpose_in(const float* __restrict__ x,
                             float* __restrict__ Y, float* __restrict__ RES,
                             f16* __restrict__ Yh) {
    __shared__ float tile[32][33];
    const int b  = blockIdx.z;
    const int t  = blockIdx.y >> 5;
    const int i  = blockIdx.y & 31;
    const int c0 = blockIdx.x << 5;
    const int tx = threadIdx.x, ty = threadIdx.y;   // (32,8)

    const float* xp = x + (((size_t)(b*CH + c0)*SEQ + t)*32 + i)*32;
#pragma unroll
    for (int r = 0; r < 4; r++) {
        int cl = ty + r*8;
        tile[cl][tx] = xp[(size_t)cl*SEQ*32*32 + tx];
    }
    __syncthreads();
#pragma unroll
    for (int r = 0; r < 4; r++) {
        int j = ty + r*8;
        size_t off = ((size_t)(b*1024 + i*32 + j)*SEQ + t)*CH + c0 + tx;
        float v = tile[tx][j];
        Y[off] = v; RES[off] = v;
        Yh[off] = __float2half_rn(v);
    }
}

// ------------------ transpose out + final mp_add ----------------------------
__global__ void transpose_out(const float* __restrict__ P,
                              const float* __restrict__ RES,
                              float* __restrict__ out) {
    __shared__ float tile[32][33];
    const int b  = blockIdx.z;
    const int t  = blockIdx.y >> 5;
    const int i  = blockIdx.y & 31;
    const int c0 = blockIdx.x << 5;
    const int tx = threadIdx.x, ty = threadIdx.y;

#pragma unroll
    for (int r = 0; r < 4; r++) {
        int j = ty + r*8;
        size_t off = ((size_t)(b*1024 + i*32 + j)*SEQ + t)*CH + c0 + tx;
        tile[tx][j] = (P[off]*0.7f + RES[off]*0.3f) * MP_INV;
    }
    __syncthreads();
    float* op = out + (((size_t)(b*CH + c0)*SEQ + t)*32 + i)*32;
#pragma unroll
    for (int r = 0; r < 4; r++) {
        int cl = ty + r*8;
        op[(size_t)cl*SEQ*32*32 + tx] = tile[cl][tx];
    }
}

// ----------------- weight row l2norm -> fp16 --------------------------------
__global__ void rownorm(const float* __restrict__ src,
                        f16* __restrict__ dst,
                        const float* __restrict__ gain) {
    const int row = blockIdx.x;
    const int t   = threadIdx.x;            // 128 threads, K=512
    const float4 v = ((const float4*)(src + (size_t)row*CH))[t];
    float ss = v.x*v.x + v.y*v.y + v.z*v.z + v.w*v.w;
#pragma unroll
    for (int o = 16; o; o >>= 1) ss += __shfl_xor_sync(0xffffffffu, ss, o);
    __shared__ float red[4];
    __shared__ float sscale;
    if ((t & 31) == 0) red[t >> 5] = ss;
    __syncthreads();
    if (t == 0) {
        float tot = red[0] + red[1] + red[2] + red[3];
        float sc = 1.f / (fmaxf(sqrtf(tot), 1e-4f) * 22.627416998f); // sqrt(512)
        if (gain) sc *= gain[0];
        sscale = sc;
    }
    __syncthreads();
    const float sc = sscale;
    union { f16 b[4]; uint2 u; } H;
    H.b[0] = __float2half_rn(v.x*sc); H.b[1] = __float2half_rn(v.y*sc);
    H.b[2] = __float2half_rn(v.z*sc); H.b[3] = __float2half_rn(v.w*sc);
    *(uint2*)(dst + (size_t)row*CH + 4*t) = H.u;
}

// ==================== mma.sync fp16 GEMM =====================================
// C[M,N] = A[M,512] @ B[N,512]^T  (A,B fp16-rounded, fp32 accum).
// CTA tile 128x128, K-chunk 64 (128B rows, SW128), cp.async TRIPLE buffer.
// 8 warps in 4(M) x 2(N); warp tile 32x64; mma m16n8k16 f16. 2 CTAs/SM.

#define TILE_B 16384               // one 128row x 128B tile
#define STAGE  (2*TILE_B)          // A, B
#define GSMEM  (3*STAGE)           // 98304 (3 stages)

__device__ __forceinline__ uint32_t sw128(uint32_t o) { return o ^ ((o >> 3) & 0x70); }

__device__ __forceinline__ void cp16(uint32_t dst, const void* src) {
    asm volatile("cp.async.cg.shared.global [%0], [%1], 16;\n" :: "r"(dst), "l"(src));
}
#define CP_COMMIT() asm volatile("cp.async.commit_group;\n" ::: "memory")
#define CP_WAIT(n)  asm volatile("cp.async.wait_group %0;\n" :: "n"(n) : "memory")

__device__ __forceinline__ void ldsm4(uint32_t (&r)[4], uint32_t addr) {
    asm volatile("ldmatrix.sync.aligned.m8n8.x4.shared.b16 {%0,%1,%2,%3}, [%4];"
                 : "=r"(r[0]), "=r"(r[1]), "=r"(r[2]), "=r"(r[3]) : "r"(addr));
}

__device__ __forceinline__ void mma16816(float (&d)[4], const uint32_t (&a)[4],
                                         const uint32_t* b) {
    asm volatile(
        "mma.sync.aligned.m16n8k16.row.col.f32.f16.f16.f32 "
        "{%0,%1,%2,%3}, {%4,%5,%6,%7}, {%8,%9}, {%0,%1,%2,%3};"
        : "+f"(d[0]), "+f"(d[1]), "+f"(d[2]), "+f"(d[3])
        : "r"(a[0]), "r"(a[1]), "r"(a[2]), "r"(a[3]), "r"(b[0]), "r"(b[1]));
}

template<int MODE>
__global__ void __launch_bounds__(256, 2)
gemm_mma(const f16* __restrict__ Ah_, const f16* __restrict__ Bh_,
         float* __restrict__ C, f16* __restrict__ Ch,
         int N) {
    extern __shared__ char smem[];
    const uint32_t sb = (uint32_t)__cvta_generic_to_shared(smem);
    const int tid   = threadIdx.x;
    const int lane  = tid & 31;
    const int warp  = tid >> 5;
    const int warpM = warp & 3;          // 0..3  -> 32-row slab
    const int warpN = warp >> 2;         // 0..1  -> 64-col slab
    const int m0 = blockIdx.y * 128;
    const int n0 = blockIdx.x * 128;

    float acc[2][8][4];
#pragma unroll
    for (int i = 0; i < 2; i++)
#pragma unroll
        for (int j = 0; j < 8; j++)
#pragma unroll
            for (int e = 0; e < 4; e++) acc[i][j][e] = 0.f;

    // ldmatrix lane addressing (within a 128B-row SW128 tile)
    const int a_row  = (lane & 15);              // + frag*16
    const int a_byte = (lane >> 4) << 4;         // + ks*32
    const int b_row  = (lane & 7) + ((lane >> 4) << 3);   // + group*16
    const int b_byte = ((lane >> 3) & 1) << 4;   // + ks*32

    // -------- chunk loader: 64 k-elements (128B rows) of A and B tiles ------
    auto load_chunk = [&](int c, int buf) {
        const uint32_t bb = sb + buf*STAGE;
        const int k0 = c * 64;
#pragma unroll
        for (int i = tid; i < 1024; i += 256) {      // 128 rows x 8 segs
            int r = i >> 3, s = i & 7;
            uint32_t o = sw128(r*128 + s*16);
            cp16(bb + o,          Ah_ + (size_t)(m0 + r)*CH + k0 + s*8);
            cp16(bb + TILE_B + o, Bh_ + (size_t)(n0 + r)*CH + k0 + s*8);
        }
        CP_COMMIT();
    };

    load_chunk(0, 0);
    load_chunk(1, 1);

    for (int c = 0; c < 8; c++) {
        if (c + 2 < 8) load_chunk(c + 2, (c + 2) % 3);
        if (c < 6)      { CP_WAIT(2); }
        else if (c == 6){ CP_WAIT(1); }
        else            { CP_WAIT(0); }
        __syncthreads();

        const uint32_t bb = sb + (c % 3)*STAGE;
#pragma unroll
        for (int ks = 0; ks < 4; ks++) {
            const int kb = ks * 32;
            uint32_t ah[2][4];
#pragma unroll
            for (int mf = 0; mf < 2; mf++) {
                uint32_t ro = (uint32_t)(warpM*32 + mf*16 + a_row)*128 + kb + a_byte;
                ldsm4(ah[mf], bb + sw128(ro));
            }
            uint32_t bh[8][2];
#pragma unroll
            for (int g = 0; g < 4; g++) {
                uint32_t ro = (uint32_t)(warpN*64 + g*16 + b_row)*128 + kb + b_byte;
                uint32_t t[4];
                ldsm4(t, bb + TILE_B + sw128(ro));
                bh[2*g][0] = t[0]; bh[2*g][1] = t[1];
                bh[2*g+1][0] = t[2]; bh[2*g+1][1] = t[3];
            }
#pragma unroll
            for (int mf = 0; mf < 2; mf++)
#pragma unroll
                for (int nf = 0; nf < 8; nf++)
                    mma16816(acc[mf][nf], ah[mf], bh[nf]);
        }
        __syncthreads();
    }

    // ------------------------------ epilogue --------------------------------
    const int mr = m0 + warpM*32 + (lane >> 2);
    const int nc = n0 + warpN*64 + (lane & 3)*2;
#pragma unroll
    for (int mf = 0; mf < 2; mf++)
#pragma unroll
        for (int nf = 0; nf < 8; nf++)
#pragma unroll
            for (int half = 0; half < 2; half++) {
                const int m = mr + mf*16 + half*8;
                const int n = nc + nf*8;
                float v0 = acc[mf][nf][half*2 + 0];
                float v1 = acc[mf][nf][half*2 + 1];
                float* Cp = C + (size_t)m*N + n;
                if (MODE == 0) {
                    *(float2*)Cp = make_float2(v0, v1);
                } else {
                    float2 old = *(const float2*)Cp;
                    v0 = (v0*0.7f + old.x*0.3f)*MP_INV;
                    v1 = (v1*0.7f + old.y*0.3f)*MP_INV;
                    *(float2*)Cp = make_float2(v0, v1);
                    union { f16 b[2]; uint32_t u; } H;
                    H.b[0] = __float2half_rn(v0);
                    H.b[1] = __float2half_rn(v1);
                    *(uint32_t*)(Ch + (size_t)m*N + n) = H.u;
                }
            }
}

// ------------------------- fused attention ----------------------------------
// 1 warp per (batch, head-pair): lanes 0-15 handle head hp, 16-31 head hp+1.
__global__ void attention(const float* __restrict__ QKV,
                          const float* __restrict__ memkv,
                          f16* __restrict__ Oh) {
    __shared__ float kn[2][KVLEN][DIMH];
    __shared__ float vn[2][KVLEN][DIMH];
    const int hp   = blockIdx.x << 1;
    const int bt   = blockIdx.y;
    const int lane = threadIdx.x;
    const float* memk = memkv;
    const float* memv = memkv + HEADS*MEM*DIMH;

#pragma unroll
    for (int idx = 0; idx < 2*KVLEN; idx++) {
        const int hh = idx / KVLEN;
        const int r  = idx % KVLEN;
        const int head = hp + hh;
        const float* ks = (r < MEM)
            ? memk + ((size_t)head*MEM + r)*DIMH
            : QKV + ((size_t)bt*SEQ + (r-MEM))*QKVN + CH + head*DIMH;
        float x0 = ks[lane], x1 = ks[lane+32];
        float ss = x0*x0 + x1*x1;
#pragma unroll
        for (int o = 16; o; o >>= 1) ss += __shfl_xor_sync(0xffffffffu, ss, o);
        float s = 8.f / fmaxf(sqrtf(ss), 1e-4f);   // pixel_norm scale
        kn[hh][r][lane] = x0*s; kn[hh][r][lane+32] = x1*s;

        const float* vs = (r < MEM)
            ? memv + ((size_t)head*MEM + r)*DIMH
            : QKV + ((size_t)bt*SEQ + (r-MEM))*QKVN + 2*CH + head*DIMH;
        x0 = vs[lane]; x1 = vs[lane+32];
        ss = x0*x0 + x1*x1;
#pragma unroll
        for (int o = 16; o; o >>= 1) ss += __shfl_xor_sync(0xffffffffu, ss, o);
        s = 8.f / fmaxf(sqrtf(ss), 1e-4f);
        vn[hh][r][lane] = x0*s; vn[hh][r][lane+32] = x1*s;
    }
    __syncwarp();

    // lanes 0-15: head hp, rows 0-15; lanes 16-31: head hp+1, rows 0-15
    const int hh  = lane >> 4;
    const int row = lane & 15;
    const int head = hp + hh;

    const float4* qp = (const float4*)(QKV + ((size_t)bt*SEQ + row)*QKVN + head*DIMH);
    float q[DIMH];
    float ss = 0.f;
#pragma unroll
    for (int d4 = 0; d4 < DIMH/4; d4++) {
        float4 v = qp[d4];
        q[4*d4+0]=v.x; q[4*d4+1]=v.y; q[4*d4+2]=v.z; q[4*d4+3]=v.w;
        ss += v.x*v.x + v.y*v.y + v.z*v.z + v.w*v.w;
    }
    const float qs = 1.f / fmaxf(sqrtf(ss), 1e-4f);  // pixel_norm(q)*D^-1/2 == l2norm

    float sc[KVLEN];
    float mx = -1e30f;
#pragma unroll
    for (int j = 0; j < KVLEN; j++) {
        float dot = 0.f;
#pragma unroll
        for (int d = 0; d < DIMH; d++) dot += q[d]*kn[hh][j][d];
        dot *= qs;
        sc[j] = dot;
        mx = fmaxf(mx, dot);
    }
    float sum = 0.f;
#pragma unroll
    for (int j = 0; j < KVLEN; j++) { sc[j] = expf(sc[j] - mx); sum += sc[j]; }
    const float inv = 1.f / sum;

    float o[DIMH];
#pragma unroll
    for (int d = 0; d < DIMH; d++) o[d] = 0.f;
#pragma unroll
    for (int j = 0; j < KVLEN; j++) {
        float p = sc[j];
#pragma unroll
        for (int d = 0; d < DIMH; d++) o[d] += p * vn[hh][j][d];
    }
    size_t base = ((size_t)bt*SEQ + row)*CH + head*DIMH;
#pragma unroll
    for (int d4 = 0; d4 < DIMH/4; d4++) {
        union { f16 b[4]; uint2 u; } H;
#pragma unroll
        for (int i = 0; i < 4; i++)
            H.b[i] = __float2half_rn(o[4*d4+i]*inv);
        *(uint2*)(Oh + base + 4*d4) = H.u;
    }
}

// ------------------------------- launcher ------------------------------------
extern "C" void kernel_launch(void* const* d_in, const int* in_sizes, int n_in,
                              void* d_out, int out_size) {
    const float* x      = (const float*)d_in[0];
    const float* w_qkv  = (const float*)d_in[1];
    const float* w_out  = (const float*)d_in[2];
    const float* mem_kv = (const float*)d_in[3];
    const float* w_proj = (const float*)d_in[4];
    const float* gain   = (const float*)d_in[5];
    float* out = (float*)d_out;

    float *Y, *RES, *QKV;
    f16 *Yh, *ATh, *Wq, *Wo, *Wp;
    cudaGetSymbolAddress((void**)&Y,   g_Y);
    cudaGetSymbolAddress((void**)&RES, g_RES);
    cudaGetSymbolAddress((void**)&QKV, g_QKV);
    cudaGetSymbolAddress((void**)&Yh,  g_Yh);
    cudaGetSymbolAddress((void**)&ATh, g_ATh);
    cudaGetSymbolAddress((void**)&Wq,  g_Wq);
    cudaGetSymbolAddress((void**)&Wo,  g_Wo);
    cudaGetSymbolAddress((void**)&Wp,  g_Wp);

    cudaFuncSetAttribute(gemm_mma<0>, cudaFuncAttributeMaxDynamicSharedMemorySize, GSMEM);
    cudaFuncSetAttribute(gemm_mma<1>, cudaFuncAttributeMaxDynamicSharedMemorySize, GSMEM);

    const dim3 tb(32, 8);
    const dim3 tg(16, 512, 2);

    transpose_in<<<tg, tb>>>(x, Y, RES, Yh);

    rownorm<<<2*QKVN, 128>>>(w_qkv,  Wq, nullptr);
    rownorm<<<2*CH,   128>>>(w_out,  Wo, nullptr);
    rownorm<<<CH,     128>>>(w_proj, Wp, gain);

    for (int l = 0; l < 2; l++) {
        gemm_mma<0><<<dim3(QKVN/128, MROWS/128), 256, GSMEM>>>(
            Yh, Wq + (size_t)l*QKVN*CH, QKV, nullptr, QKVN);
        attention<<<dim3(HEADS/2, BATCH), 32>>>(
            QKV, mem_kv + (size_t)l*2*HEADS*MEM*DIMH, ATh);
        gemm_mma<1><<<dim3(CH/128, MROWS/128), 256, GSMEM>>>(
            ATh, Wo + (size_t)l*CH*CH, Y, Yh, CH);
    }

    gemm_mma<0><<<dim3(CH/128, MROWS/128), 256, GSMEM>>>(
        Yh, Wp, QKV, nullptr, CH);
    transpose_out<<<tg, tb>>>(QKV, RES, out);
}